// round 15
// baseline (speedup 1.0000x reference)
#include <cuda_runtime.h>
#include <math.h>

#define EPSF 1e-6f
#define SCALEF 0.07216878364870323f  // 1/sqrt(192)

// ---------------- device scratch ----------------
__device__ float g_qa[32 * 1536];
__device__ float g_kv[32 * 576];
__device__ float g_kvlat[32 * 512];
__device__ float g_kpe[32 * 64];
__device__ float g_q[32 * 24576];
__device__ float g_qeff[32 * 128 * 576];
__device__ float g_scores[32 * 128 * 2048];  // also reused as W_UV partial scratch
__device__ float g_headout[32 * 16384];
__device__ float g_part[8 * 1024 * 1024];
__device__ float g_rowm[4096];
__device__ float g_rowi[4096];
__device__ float g_pm[4096 * 16];
__device__ float g_ps[4096 * 16];

// ---------------- tf32 helpers ----------------
__device__ __forceinline__ unsigned f2tf(float f) {
    unsigned u;
    asm("cvt.rna.tf32.f32 %0, %1;" : "=r"(u) : "f"(f));
    return u;
}
__device__ __forceinline__ void mma_tf32(float c[4],
                                         unsigned a0, unsigned a1, unsigned a2, unsigned a3,
                                         unsigned b0, unsigned b1) {
    asm volatile("mma.sync.aligned.m16n8k8.row.col.f32.tf32.tf32.f32 "
                 "{%0,%1,%2,%3}, {%4,%5,%6,%7}, {%8,%9}, {%0,%1,%2,%3};"
                 : "+f"(c[0]), "+f"(c[1]), "+f"(c[2]), "+f"(c[3])
                 : "r"(a0), "r"(a1), "r"(a2), "r"(a3), "r"(b0), "r"(b1));
}

// =====================================================================
// tf32 MMA GEMM (double-buffered, 32x128 tile, BK=32)
// =====================================================================
__global__ __launch_bounds__(256) void mma_gemm32(
    const float* __restrict__ A, int lda, long sA,
    const float* __restrict__ B, int ldb, long sB,
    float* __restrict__ C, int ldc, long sC,
    long partStride, int K, int N, int kchunk)
{
    __shared__ unsigned As[2][32][36];
    __shared__ unsigned Bs[2][32][132];

    const int t = threadIdx.x, lane = t & 31, wid = t >> 5;
    const int warp_m = wid >> 2, warp_n = wid & 3;
    const int lq = lane >> 2, lr = lane & 3;
    const int col0 = blockIdx.x * 128;
    const int k0b = blockIdx.y * kchunk;
    const int kend = min(K, k0b + kchunk);
    const int nIter = (kend - k0b) >> 5;

    A += (long)blockIdx.z * sA;
    B += (long)blockIdx.z * sB;
    C += (long)blockIdx.z * sC + (long)blockIdx.y * partStride;

    const int am = t >> 3, akq = (t & 7) * 4;
    const int bn = (t & 31) * 4;
    const int bkb = t >> 5;
    const bool bok = (col0 + bn < N);

    float4 fa, fb[4];
    fa = *reinterpret_cast<const float4*>(&A[(long)am * lda + k0b + akq]);
#pragma unroll
    for (int i = 0; i < 4; i++) {
        int bk = bkb + i * 8;
        fb[i] = bok ? *reinterpret_cast<const float4*>(&B[(long)(k0b + bk) * ldb + col0 + bn])
                    : make_float4(0.f, 0.f, 0.f, 0.f);
    }
    *reinterpret_cast<uint4*>(&As[0][am][akq]) =
        make_uint4(f2tf(fa.x), f2tf(fa.y), f2tf(fa.z), f2tf(fa.w));
#pragma unroll
    for (int i = 0; i < 4; i++) {
        int bk = bkb + i * 8;
        *reinterpret_cast<uint4*>(&Bs[0][bk][bn]) =
            make_uint4(f2tf(fb[i].x), f2tf(fb[i].y), f2tf(fb[i].z), f2tf(fb[i].w));
    }
    __syncthreads();

    float acc[4][4];
#pragma unroll
    for (int i = 0; i < 4; i++)
#pragma unroll
        for (int j = 0; j < 4; j++) acc[i][j] = 0.f;

    for (int it = 0; it < nIter; it++) {
        const int cur = it & 1, nxt = cur ^ 1;
        const bool hasNext = (it + 1 < nIter);
        if (hasNext) {
            int kn = k0b + (it + 1) * 32;
            fa = *reinterpret_cast<const float4*>(&A[(long)am * lda + kn + akq]);
            if (bok) {
#pragma unroll
                for (int i = 0; i < 4; i++) {
                    int bk = bkb + i * 8;
                    fb[i] = *reinterpret_cast<const float4*>(&B[(long)(kn + bk) * ldb + col0 + bn]);
                }
            }
        }
#pragma unroll
        for (int kk = 0; kk < 32; kk += 8) {
            int ar = warp_m * 16 + lq;
            int ak = kk + lr;
            unsigned a0 = As[cur][ar][ak], a1 = As[cur][ar + 8][ak];
            unsigned a2 = As[cur][ar][ak + 4], a3 = As[cur][ar + 8][ak + 4];
#pragma unroll
            for (int nt8 = 0; nt8 < 4; nt8++) {
                int bnn = warp_n * 32 + nt8 * 8 + lq;
                unsigned b0 = Bs[cur][kk + lr][bnn];
                unsigned b1 = Bs[cur][kk + 4 + lr][bnn];
                mma_tf32(acc[nt8], a0, a1, a2, a3, b0, b1);
            }
        }
        if (hasNext) {
            *reinterpret_cast<uint4*>(&As[nxt][am][akq]) =
                make_uint4(f2tf(fa.x), f2tf(fa.y), f2tf(fa.z), f2tf(fa.w));
#pragma unroll
            for (int i = 0; i < 4; i++) {
                int bk = bkb + i * 8;
                *reinterpret_cast<uint4*>(&Bs[nxt][bk][bn]) =
                    make_uint4(f2tf(fb[i].x), f2tf(fb[i].y), f2tf(fb[i].z), f2tf(fb[i].w));
            }
        }
        __syncthreads();
    }
    const int row = warp_m * 16 + lq;
#pragma unroll
    for (int nt8 = 0; nt8 < 4; nt8++) {
        int col = col0 + warp_n * 32 + nt8 * 8 + 2 * lr;
        if (col < N) {
            *reinterpret_cast<float2*>(&C[(long)row * ldc + col]) =
                make_float2(acc[nt8][0], acc[nt8][1]);
            *reinterpret_cast<float2*>(&C[(long)(row + 8) * ldc + col]) =
                make_float2(acc[nt8][2], acc[nt8][3]);
        }
    }
}

// ---------------- split-K reduce ----------------
__global__ void reduce_kernel(float* __restrict__ out,
                              const float* __restrict__ part,
                              int S, long total, long stride) {
    long i = (long)blockIdx.x * 256 + threadIdx.x;
    if (i >= total) return;
    float s = 0.f;
    for (int k = 0; k < S; k++) s += part[(long)k * stride + i];
    out[i] = s;
}

// =====================================================================
// fp32 small GEMM with fused 4-way A-partial summation (W_UV)
// =====================================================================
template <int BN>
__global__ __launch_bounds__(128) void smallgemm8s(
    const float* __restrict__ A, int lda, long sA, long sumStride,
    const float* __restrict__ B, int ldb, long sB,
    float* __restrict__ C, int ldc, long sC,
    long partStride, int K, int N, int kchunk)
{
    constexpr int CN = BN / 32;
    __shared__ float As[32][36];
    __shared__ float Bs[32][BN];

    const int t = threadIdx.x;
    const int tr = t >> 5;
    const int tc = t & 31;
    const int col0 = blockIdx.x * BN;
    const int k0b = blockIdx.y * kchunk;
    const int kend = min(K, k0b + kchunk);

    A += (long)blockIdx.z * sA;
    B += (long)blockIdx.z * sB;
    C += (long)blockIdx.z * sC + (long)blockIdx.y * partStride;

    float acc[8][CN];
#pragma unroll
    for (int i = 0; i < 8; i++)
#pragma unroll
        for (int j = 0; j < CN; j++) acc[i][j] = 0.f;

    for (int k0 = k0b; k0 < kend; k0 += 32) {
#pragma unroll
        for (int i = 0; i < 2; i++) {
            int e = t + i * 128;
            int m = e >> 3, kk0 = (e & 7) * 4;
            long idx = (long)m * lda + k0 + kk0;
            float4 v = *reinterpret_cast<const float4*>(&A[idx]);
#pragma unroll
            for (int s = 1; s < 4; s++) {
                float4 w = *reinterpret_cast<const float4*>(&A[s * sumStride + idx]);
                v.x += w.x; v.y += w.y; v.z += w.z; v.w += w.w;
            }
            *reinterpret_cast<float4*>(&As[m][kk0]) = v;
        }
#pragma unroll
        for (int i = 0; i < BN / 16; i++) {
            int e = t + i * 128;
            int kk = e / (BN / 4);
            int n0 = (e % (BN / 4)) * 4;
            float4 v = make_float4(0.f, 0.f, 0.f, 0.f);
            if (col0 + n0 < N)
                v = *reinterpret_cast<const float4*>(&B[(long)(k0 + kk) * ldb + col0 + n0]);
            *reinterpret_cast<float4*>(&Bs[kk][n0]) = v;
        }
        __syncthreads();
#pragma unroll
        for (int kk = 0; kk < 32; kk++) {
            float a[8];
#pragma unroll
            for (int i = 0; i < 8; i++) a[i] = As[tr * 8 + i][kk];
            float bfr[CN];
#pragma unroll
            for (int j4 = 0; j4 < CN / 4; j4++)
                *reinterpret_cast<float4*>(&bfr[j4 * 4]) =
                    *reinterpret_cast<const float4*>(&Bs[kk][tc * CN + j4 * 4]);
#pragma unroll
            for (int i = 0; i < 8; i++)
#pragma unroll
                for (int j = 0; j < CN; j++) acc[i][j] += a[i] * bfr[j];
        }
        __syncthreads();
    }
#pragma unroll
    for (int i = 0; i < 8; i++) {
        int m = tr * 8 + i;
#pragma unroll
        for (int j4 = 0; j4 < CN / 4; j4++) {
            int col = col0 + tc * CN + j4 * 4;
            if (col < N) {
                float4 v = make_float4(acc[i][j4 * 4], acc[i][j4 * 4 + 1],
                                       acc[i][j4 * 4 + 2], acc[i][j4 * 4 + 3]);
                *reinterpret_cast<float4*>(&C[(long)m * ldc + col]) = v;
            }
        }
    }
}

// ---------------- norms + k_pe rope ----------------
__global__ void norm_rope_kernel(float* __restrict__ qa_io,
                                 const float* __restrict__ kv_in,
                                 float* __restrict__ kvlat,
                                 float* __restrict__ kpe,
                                 const float* __restrict__ q_ln_w,
                                 const float* __restrict__ kv_ln_w,
                                 const float* __restrict__ cosd,
                                 const float* __restrict__ sind) {
    const int b = blockIdx.x;
    const int t = threadIdx.x;
    __shared__ float sd[256];

    float* qa = qa_io + b * 1536;
    float ss = 0.f;
    for (int i = t; i < 1536; i += 256) { float v = qa[i]; ss += v * v; }
    sd[t] = ss; __syncthreads();
    for (int o = 128; o > 0; o >>= 1) { if (t < o) sd[t] += sd[t + o]; __syncthreads(); }
    float r = rsqrtf(sd[0] / 1536.f + EPSF);
    __syncthreads();
    for (int i = t; i < 1536; i += 256) qa[i] = qa[i] * r * q_ln_w[i];

    const float* kv = kv_in + b * 576;
    ss = 0.f;
    for (int i = t; i < 512; i += 256) { float v = kv[i]; ss += v * v; }
    sd[t] = ss; __syncthreads();
    for (int o = 128; o > 0; o >>= 1) { if (t < o) sd[t] += sd[t + o]; __syncthreads(); }
    float r2 = rsqrtf(sd[0] / 512.f + EPSF);
    __syncthreads();
    for (int i = t; i < 512; i += 256) kvlat[b * 512 + i] = kv[i] * r2 * kv_ln_w[i];

    if (t < 32) {
        float x1 = kv[512 + 2 * t], x2 = kv[512 + 2 * t + 1];
        float c = cosd[b * 32 + t], s = sind[b * 32 + t];
        kpe[b * 64 + 2 * t]     = x1 * c - x2 * s;
        kpe[b * 64 + 2 * t + 1] = x2 * c + x1 * s;
    }
}

// ---------------- rope q_pe into g_qeff[...,512:576] ----------------
__global__ void qpe_rope_kernel(const float* __restrict__ q,
                                const float* __restrict__ cosd,
                                const float* __restrict__ sind,
                                float* __restrict__ qeff) {
    int idx = blockIdx.x * 256 + threadIdx.x;
    int b = idx >> 7, h = idx & 127;
    const float* src = q + b * 24576 + h * 192 + 128;
    float* dst = qeff + (long)(b * 128 + h) * 576 + 512;
#pragma unroll
    for (int i = 0; i < 32; i++) {
        float x1 = src[2 * i], x2 = src[2 * i + 1];
        float c = cosd[b * 32 + i], s = sind[b * 32 + i];
        dst[2 * i]     = x1 * c - x2 * s;
        dst[2 * i + 1] = x2 * c + x1 * s;
    }
}

// =====================================================================
// scores (tf32 MMA, M=128, BK=32, dynamic smem) + fused row stats.
// smem: As[2][128][36] @0 (9216u), Bs[2][32][132] @9216 (8448u) = 70656B
// =====================================================================
#define SC_AS(buf, r, k) smu[(buf) * 4608 + (r) * 36 + (k)]
#define SC_BS(buf, k, n) smu[9216 + (buf) * 4224 + (k) * 132 + (n)]

__global__ __launch_bounds__(256) void mma_scores128(
    const float* __restrict__ qeff,
    const float* __restrict__ kvlat,
    const float* __restrict__ kpe,
    const float* __restrict__ cache_kv,
    const float* __restrict__ cache_pe,
    const int* __restrict__ block_table,
    const int* __restrict__ slot_mapping,
    const int* __restrict__ seq_lens,
    float* __restrict__ scores,
    float* __restrict__ pm,
    float* __restrict__ ps)
{
    extern __shared__ unsigned smu[];
    const int nt = blockIdx.x, b = blockIdx.y;
    const int t = threadIdx.x, lane = t & 31, wid = t >> 5;
    const int warp_m = wid >> 1, warp_n = wid & 1;
    const int lq = lane >> 2, lr = lane & 3;

    const int blkid = block_table[b * 16 + nt];
    const int slotm = slot_mapping[b];
    const int ovr = ((slotm >> 7) == blkid) ? (slotm & 127) : -1;

    const float* Ab = qeff + (long)b * 73728;
    const float* kvb = cache_kv + (long)blkid * 65536;
    const float* peb = cache_pe + (long)blkid * 8192;

    auto fetchB = [&](int n, int kq) -> float4 {
        if (kq < 512) {
            return (n == ovr)
                ? *reinterpret_cast<const float4*>(&kvlat[b * 512 + kq])
                : *reinterpret_cast<const float4*>(&kvb[(long)n * 512 + kq]);
        } else {
            return (n == ovr)
                ? *reinterpret_cast<const float4*>(&kpe[b * 64 + (kq - 512)])
                : *reinterpret_cast<const float4*>(&peb[(long)n * 64 + (kq - 512)]);
        }
    };

    float4 fa[4], fb[4];
    // prologue fetch k=[0,32)
#pragma unroll
    for (int i = 0; i < 4; i++) {
        int e = t + i * 256;
        fa[i] = *reinterpret_cast<const float4*>(&Ab[(long)(e >> 3) * 576 + (e & 7) * 4]);
    }
#pragma unroll
    for (int i = 0; i < 4; i++) {
        int h = i >> 1, e2 = t + (i & 1) * 256;
        fb[i] = fetchB(e2 >> 2, (e2 & 3) * 4 + h * 16);
    }
#pragma unroll
    for (int i = 0; i < 4; i++) {
        int e = t + i * 256;
        *reinterpret_cast<uint4*>(&SC_AS(0, e >> 3, (e & 7) * 4)) =
            make_uint4(f2tf(fa[i].x), f2tf(fa[i].y), f2tf(fa[i].z), f2tf(fa[i].w));
    }
#pragma unroll
    for (int i = 0; i < 4; i++) {
        int h = i >> 1, e2 = t + (i & 1) * 256;
        int n = e2 >> 2, kq = (e2 & 3) * 4 + h * 16;
        SC_BS(0, kq + 0, n) = f2tf(fb[i].x); SC_BS(0, kq + 1, n) = f2tf(fb[i].y);
        SC_BS(0, kq + 2, n) = f2tf(fb[i].z); SC_BS(0, kq + 3, n) = f2tf(fb[i].w);
    }
    __syncthreads();

    float acc[2][8][4];
#pragma unroll
    for (int m = 0; m < 2; m++)
#pragma unroll
        for (int i = 0; i < 8; i++)
#pragma unroll
            for (int j = 0; j < 4; j++) acc[m][i][j] = 0.f;

    const int nIter = 18;  // 576 / 32
    for (int it = 0; it < nIter; it++) {
        const int cur = it & 1, nxt = cur ^ 1;
        const bool hn = (it + 1 < nIter);
        if (hn) {
            int kn = (it + 1) * 32;
#pragma unroll
            for (int i = 0; i < 4; i++) {
                int e = t + i * 256;
                fa[i] = *reinterpret_cast<const float4*>(
                    &Ab[(long)(e >> 3) * 576 + kn + (e & 7) * 4]);
            }
#pragma unroll
            for (int i = 0; i < 4; i++) {
                int h = i >> 1, e2 = t + (i & 1) * 256;
                fb[i] = fetchB(e2 >> 2, kn + (e2 & 3) * 4 + h * 16);
            }
        }
#pragma unroll
        for (int kk = 0; kk < 32; kk += 8) {
            int ak = kk + lr;
            unsigned a[2][4];
#pragma unroll
            for (int m = 0; m < 2; m++) {
                int ar = warp_m * 32 + m * 16 + lq;
                a[m][0] = SC_AS(cur, ar, ak);      a[m][1] = SC_AS(cur, ar + 8, ak);
                a[m][2] = SC_AS(cur, ar, ak + 4);  a[m][3] = SC_AS(cur, ar + 8, ak + 4);
            }
#pragma unroll
            for (int nf = 0; nf < 8; nf++) {
                int bn = warp_n * 64 + nf * 8 + lq;
                unsigned b0 = SC_BS(cur, kk + lr, bn);
                unsigned b1 = SC_BS(cur, kk + 4 + lr, bn);
                mma_tf32(acc[0][nf], a[0][0], a[0][1], a[0][2], a[0][3], b0, b1);
                mma_tf32(acc[1][nf], a[1][0], a[1][1], a[1][2], a[1][3], b0, b1);
            }
        }
        if (hn) {
#pragma unroll
            for (int i = 0; i < 4; i++) {
                int e = t + i * 256;
                *reinterpret_cast<uint4*>(&SC_AS(nxt, e >> 3, (e & 7) * 4)) =
                    make_uint4(f2tf(fa[i].x), f2tf(fa[i].y), f2tf(fa[i].z), f2tf(fa[i].w));
            }
#pragma unroll
            for (int i = 0; i < 4; i++) {
                int h = i >> 1, e2 = t + (i & 1) * 256;
                int n = e2 >> 2, kq = (e2 & 3) * 4 + h * 16;
                SC_BS(nxt, kq + 0, n) = f2tf(fb[i].x); SC_BS(nxt, kq + 1, n) = f2tf(fb[i].y);
                SC_BS(nxt, kq + 2, n) = f2tf(fb[i].z); SC_BS(nxt, kq + 3, n) = f2tf(fb[i].w);
            }
        }
        __syncthreads();
    }

    // ------------- epilogue: scores write + fused per-block row stats -------
    float* smax = reinterpret_cast<float*>(smu);   // [128][2]
    float* ssum = smax + 256;                      // [128][2]
    const int L = seq_lens[b];

#pragma unroll
    for (int m = 0; m < 2; m++) {
        float m0 = -1e30f, m1 = -1e30f;
#pragma unroll
        for (int nf = 0; nf < 8; nf++) {
            int col = nt * 128 + warp_n * 64 + nf * 8 + 2 * lr;
            float v00 = (col < L)     ? acc[m][nf][0] * SCALEF : -1e30f;
            float v01 = (col + 1 < L) ? acc[m][nf][1] * SCALEF : -1e30f;
            float v10 = (col < L)     ? acc[m][nf][2] * SCALEF : -1e30f;
            float v11 = (col + 1 < L) ? acc[m][nf][3] * SCALEF : -1e30f;
            m0 = fmaxf(m0, fmaxf(v00, v01));
            m1 = fmaxf(m1, fmaxf(v10, v11));
        }
        m0 = fmaxf(m0, __shfl_xor_sync(0xffffffffu, m0, 1));
        m0 = fmaxf(m0, __shfl_xor_sync(0xffffffffu, m0, 2));
        m1 = fmaxf(m1, __shfl_xor_sync(0xffffffffu, m1, 1));
        m1 = fmaxf(m1, __shfl_xor_sync(0xffffffffu, m1, 2));
        if (lr == 0) {
            int rl0 = warp_m * 32 + m * 16 + lq;
            smax[rl0 * 2 + warp_n] = m0;
            smax[(rl0 + 8) * 2 + warp_n] = m1;
        }
    }
    __syncthreads();

#pragma unroll
    for (int m = 0; m < 2; m++) {
        int rl0 = warp_m * 32 + m * 16 + lq;
        float rm0 = fmaxf(smax[rl0 * 2], smax[rl0 * 2 + 1]);
        float rm1 = fmaxf(smax[(rl0 + 8) * 2], smax[(rl0 + 8) * 2 + 1]);
        float s0 = 0.f, s1 = 0.f;
        const long row0 = (long)(b * 128 + rl0);
#pragma unroll
        for (int nf = 0; nf < 8; nf++) {
            int col = nt * 128 + warp_n * 64 + nf * 8 + 2 * lr;
            float v00 = acc[m][nf][0] * SCALEF, v01 = acc[m][nf][1] * SCALEF;
            float v10 = acc[m][nf][2] * SCALEF, v11 = acc[m][nf][3] * SCALEF;
            if (col < L)     { s0 += __expf(v00 - rm0); s1 += __expf(v10 - rm1); }
            if (col + 1 < L) { s0 += __expf(v01 - rm0); s1 += __expf(v11 - rm1); }
            *reinterpret_cast<float2*>(&scores[row0 * 2048 + col]) = make_float2(v00, v01);
            *reinterpret_cast<float2*>(&scores[(row0 + 8) * 2048 + col]) = make_float2(v10, v11);
        }
        s0 += __shfl_xor_sync(0xffffffffu, s0, 1);
        s0 += __shfl_xor_sync(0xffffffffu, s0, 2);
        s1 += __shfl_xor_sync(0xffffffffu, s1, 1);
        s1 += __shfl_xor_sync(0xffffffffu, s1, 2);
        if (lr == 0) {
            ssum[rl0 * 2 + warp_n] = s0;
            ssum[(rl0 + 8) * 2 + warp_n] = s1;
        }
    }
    __syncthreads();

    if (warp_n == 0 && lr == 0) {
#pragma unroll
        for (int m = 0; m < 2; m++) {
            int rl0 = warp_m * 32 + m * 16 + lq;
            int rl1 = rl0 + 8;
            float rm0 = fmaxf(smax[rl0 * 2], smax[rl0 * 2 + 1]);
            float rm1 = fmaxf(smax[rl1 * 2], smax[rl1 * 2 + 1]);
            pm[(long)(b * 128 + rl0) * 16 + nt] = rm0;
            pm[(long)(b * 128 + rl1) * 16 + nt] = rm1;
            ps[(long)(b * 128 + rl0) * 16 + nt] = ssum[rl0 * 2] + ssum[rl0 * 2 + 1];
            ps[(long)(b * 128 + rl1) * 16 + nt] = ssum[rl1 * 2] + ssum[rl1 * 2 + 1];
        }
    }
}

// ---------------- combine per-block partials -> rowM, rowI ----------------
__global__ void combine_rowstat(const float* __restrict__ pm,
                                const float* __restrict__ ps,
                                float* __restrict__ rowM,
                                float* __restrict__ rowI) {
    int row = blockIdx.x * 256 + threadIdx.x;
    if (row >= 4096) return;
    float M = -1e30f;
#pragma unroll
    for (int i = 0; i < 16; i++) M = fmaxf(M, pm[row * 16 + i]);
    float S = 0.f;
#pragma unroll
    for (int i = 0; i < 16; i++) S += ps[row * 16 + i] * __expf(pm[row * 16 + i] - M);
    rowM[row] = M;
    rowI[row] = 1.f / S;
}

// =====================================================================
// ctx (tf32 MMA, M=128, BK=32, dynamic smem, fused softmax staging)
// smem: As[2][128][36] @0, Bs[2][32][132] @9216, srm/sri @17664 = 71680B
// =====================================================================
__global__ __launch_bounds__(256) void mma_ctx128(
    const float* __restrict__ scores,
    const float* __restrict__ kvlat,
    const float* __restrict__ cache_kv,
    const int* __restrict__ block_table,
    const int* __restrict__ slot_mapping,
    const int* __restrict__ seq_lens,
    const float* __restrict__ rowM,
    const float* __restrict__ rowI,
    float* __restrict__ part)
{
    extern __shared__ unsigned smu[];
    float* srm = reinterpret_cast<float*>(smu + 17664);
    float* sri = srm + 128;

    const int nt = blockIdx.x, sk = blockIdx.y, b = blockIdx.z;
    const int t = threadIdx.x, lane = t & 31, wid = t >> 5;
    const int warp_m = wid >> 1, warp_n = wid & 1;
    const int lq = lane >> 2, lr = lane & 3;
    const int slotm = slot_mapping[b];
    const int ovrBlk = slotm >> 7, ovrOff = slotm & 127;
    const int L = seq_lens[b];
    const int tk0 = sk * 512;

    if (t < 128) { srm[t] = rowM[b * 128 + t]; sri[t] = rowI[b * 128 + t]; }
    __syncthreads();

    auto fetchB = [&](int k0, int kk, int n0) -> float4 {
        int tok = tk0 + k0 + kk;
        int blkid = block_table[b * 16 + (tok >> 7)];
        int soff = tok & 127;
        if (blkid == ovrBlk && soff == ovrOff)
            return *reinterpret_cast<const float4*>(&kvlat[b * 512 + nt * 128 + n0]);
        return *reinterpret_cast<const float4*>(
            &cache_kv[(long)(blkid * 128 + soff) * 512 + nt * 128 + n0]);
    };

    auto xformA = [&](float4 v, float rm, float ri, int kbase) -> uint4 {
        float e0 = (kbase + 0 < L) ? __expf(v.x - rm) * ri : 0.f;
        float e1 = (kbase + 1 < L) ? __expf(v.y - rm) * ri : 0.f;
        float e2 = (kbase + 2 < L) ? __expf(v.z - rm) * ri : 0.f;
        float e3 = (kbase + 3 < L) ? __expf(v.w - rm) * ri : 0.f;
        return make_uint4(f2tf(e0), f2tf(e1), f2tf(e2), f2tf(e3));
    };

    float4 fa[4], fb[4];
#pragma unroll
    for (int i = 0; i < 4; i++) {
        int e = t + i * 256;
        fa[i] = *reinterpret_cast<const float4*>(
            &scores[(long)(b * 128 + (e >> 3)) * 2048 + tk0 + (e & 7) * 4]);
        fb[i] = fetchB(0, e >> 5, (e & 31) * 4);
    }
#pragma unroll
    for (int i = 0; i < 4; i++) {
        int e = t + i * 256;
        int r = e >> 3, kq = (e & 7) * 4;
        *reinterpret_cast<uint4*>(&SC_AS(0, r, kq)) =
            xformA(fa[i], srm[r], sri[r], tk0 + kq);
        *reinterpret_cast<uint4*>(&SC_BS(0, e >> 5, (e & 31) * 4)) =
            make_uint4(f2tf(fb[i].x), f2tf(fb[i].y), f2tf(fb[i].z), f2tf(fb[i].w));
    }
    __syncthreads();

    float acc[2][8][4];
#pragma unroll
    for (int m = 0; m < 2; m++)
#pragma unroll
        for (int i = 0; i < 8; i++)
#pragma unroll
            for (int j = 0; j < 4; j++) acc[m][i][j] = 0.f;

    const int nIter = 16;  // 512 / 32
    for (int it = 0; it < nIter; it++) {
        const int cur = it & 1, nxt = cur ^ 1;
        const bool hn = (it + 1 < nIter);
        int kn = (it + 1) * 32;
        if (hn) {
#pragma unroll
            for (int i = 0; i < 4; i++) {
                int e = t + i * 256;
                fa[i] = *reinterpret_cast<const float4*>(
                    &scores[(long)(b * 128 + (e >> 3)) * 2048 + tk0 + kn + (e & 7) * 4]);
                fb[i] = fetchB(kn, e >> 5, (e & 31) * 4);
            }
        }
#pragma unroll
        for (int kk = 0; kk < 32; kk += 8) {
            int ak = kk + lr;
            unsigned a[2][4];
#pragma unroll
            for (int m = 0; m < 2; m++) {
                int ar = warp_m * 32 + m * 16 + lq;
                a[m][0] = SC_AS(cur, ar, ak);      a[m][1] = SC_AS(cur, ar + 8, ak);
                a[m][2] = SC_AS(cur, ar, ak + 4);  a[m][3] = SC_AS(cur, ar + 8, ak + 4);
            }
#pragma unroll
            for (int nf = 0; nf < 8; nf++) {
                int bn = warp_n * 64 + nf * 8 + lq;
                unsigned b0 = SC_BS(cur, kk + lr, bn);
                unsigned b1 = SC_BS(cur, kk + 4 + lr, bn);
                mma_tf32(acc[0][nf], a[0][0], a[0][1], a[0][2], a[0][3], b0, b1);
                mma_tf32(acc[1][nf], a[1][0], a[1][1], a[1][2], a[1][3], b0, b1);
            }
        }
        if (hn) {
#pragma unroll
            for (int i = 0; i < 4; i++) {
                int e = t + i * 256;
                int r = e >> 3, kq = (e & 7) * 4;
                *reinterpret_cast<uint4*>(&SC_AS(nxt, r, kq)) =
                    xformA(fa[i], srm[r], sri[r], tk0 + kn + kq);
                *reinterpret_cast<uint4*>(&SC_BS(nxt, e >> 5, (e & 31) * 4)) =
                    make_uint4(f2tf(fb[i].x), f2tf(fb[i].y), f2tf(fb[i].z), f2tf(fb[i].w));
            }
        }
        __syncthreads();
    }
    float* outp = part + (long)sk * 2097152;
#pragma unroll
    for (int m = 0; m < 2; m++) {
        const long row0 = (long)(b * 128 + warp_m * 32 + m * 16 + lq);
#pragma unroll
        for (int nf = 0; nf < 8; nf++) {
            int col = nt * 128 + warp_n * 64 + nf * 8 + 2 * lr;
            *reinterpret_cast<float2*>(&outp[row0 * 512 + col]) =
                make_float2(acc[m][nf][0], acc[m][nf][1]);
            *reinterpret_cast<float2*>(&outp[(row0 + 8) * 512 + col]) =
                make_float2(acc[m][nf][2], acc[m][nf][3]);
        }
    }
}

// ------------------------------ host driver ------------------------------
extern "C" void kernel_launch(void* const* d_in, const int* in_sizes, int n_in,
                              void* d_out, int out_size) {
    const float* hidden    = (const float*)d_in[0];
    const float* cosd      = (const float*)d_in[1];
    const float* sind      = (const float*)d_in[2];
    const float* Wq_a      = (const float*)d_in[3];
    const float* q_ln_w    = (const float*)d_in[4];
    const float* Wq_b      = (const float*)d_in[5];
    const float* Wkv_a     = (const float*)d_in[6];
    const float* kv_ln_w   = (const float*)d_in[7];
    const float* Wukt      = (const float*)d_in[8];
    const float* Wuv       = (const float*)d_in[9];
    const float* Wo        = (const float*)d_in[10];
    const float* cache_kv  = (const float*)d_in[11];
    const float* cache_pe  = (const float*)d_in[12];
    const int*   block_tab = (const int*)d_in[13];
    const int*   slot_map  = (const int*)d_in[14];
    const int*   seq_lens  = (const int*)d_in[15];
    float* out = (float*)d_out;

    float *qa, *kvb, *kvlat, *kpe, *q, *qeff, *scores, *headout, *part;
    float *rowm, *rowi, *pm, *ps;
    cudaGetSymbolAddress((void**)&qa,      g_qa);
    cudaGetSymbolAddress((void**)&kvb,     g_kv);
    cudaGetSymbolAddress((void**)&kvlat,   g_kvlat);
    cudaGetSymbolAddress((void**)&kpe,     g_kpe);
    cudaGetSymbolAddress((void**)&q,       g_q);
    cudaGetSymbolAddress((void**)&qeff,    g_qeff);
    cudaGetSymbolAddress((void**)&scores,  g_scores);
    cudaGetSymbolAddress((void**)&headout, g_headout);
    cudaGetSymbolAddress((void**)&part,    g_part);
    cudaGetSymbolAddress((void**)&rowm,    g_rowm);
    cudaGetSymbolAddress((void**)&rowi,    g_rowi);
    cudaGetSymbolAddress((void**)&pm,      g_pm);
    cudaGetSymbolAddress((void**)&ps,      g_ps);

    const int SC_SMEM = 17664 * 4;  // 70656 B
    const int CX_SMEM = 17920 * 4;  // 71680 B
    cudaFuncSetAttribute(mma_scores128, cudaFuncAttributeMaxDynamicSharedMemorySize, SC_SMEM);
    cudaFuncSetAttribute(mma_ctx128,    cudaFuncAttributeMaxDynamicSharedMemorySize, CX_SMEM);

    // 1) q_a = hidden @ Wq_a  (K=5120, N=1536), splitK 16 x 320
    mma_gemm32<<<dim3(12, 16, 1), 256>>>(hidden, 5120, 0, Wq_a, 1536, 0,
                                         part, 1536, 0, 49152, 5120, 1536, 320);
    reduce_kernel<<<(49152 + 255) / 256, 256>>>(qa, part, 16, 49152, 49152);

    // 2) kv = hidden @ Wkv_a  (K=5120, N=576), splitK 16 x 320
    mma_gemm32<<<dim3(5, 16, 1), 256>>>(hidden, 5120, 0, Wkv_a, 576, 0,
                                        part, 576, 0, 18432, 5120, 576, 320);
    reduce_kernel<<<(18432 + 255) / 256, 256>>>(kvb, part, 16, 18432, 18432);

    // 3) norms + k_pe rope
    norm_rope_kernel<<<32, 256>>>(qa, kvb, kvlat, kpe, q_ln_w, kv_ln_w, cosd, sind);

    // 4) q = q_a_norm @ Wq_b  (K=1536, N=24576), splitK 2 x 768
    mma_gemm32<<<dim3(192, 2, 1), 256>>>(qa, 1536, 0, Wq_b, 24576, 0,
                                         part, 24576, 0, 786432, 1536, 24576, 768);
    reduce_kernel<<<(786432 + 255) / 256, 256>>>(q, part, 2, 786432, 786432);

    // 5) rope q_pe -> qeff[..., 512:576]
    qpe_rope_kernel<<<16, 256>>>(q, cosd, sind, qeff);

    // 6) q_lat[b,h,:512] = q_nope[b,h] @ W_UK_T[h]  (per-head, tf32 MMA)
    mma_gemm32<<<dim3(4, 1, 128), 256>>>(q, 24576, 192, Wukt, 512, 65536,
                                         qeff, 73728, 576, 0, 128, 512, 128);

    // 7) attention scores + fused per-block row stats (BK=32, 512 CTAs)
    mma_scores128<<<dim3(16, 32), 256, SC_SMEM>>>(qeff, kvlat, kpe, cache_kv,
                                                  cache_pe, block_tab, slot_map,
                                                  seq_lens, scores, pm, ps);

    // 8) combine partials -> rowM, rowI
    combine_rowstat<<<16, 256>>>(pm, ps, rowm, rowi);

    // 9) ctx partials = softmax(scores) @ keys_kv (BK=32, token splitK 4)
    mma_ctx128<<<dim3(4, 4, 32), 256, CX_SMEM>>>(scores, kvlat, cache_kv,
                                                 block_tab, slot_map, seq_lens,
                                                 rowm, rowi, part);

    // 10) headout = (sum of ctx partials) @ W_UV, fused A-sum
    smallgemm8s<128><<<dim3(1, 4, 128), 128>>>(part, 65536, 512, 2097152,
                                               Wuv, 128, 65536,
                                               scores, 16384, 128, 524288,
                                               512, 128, 128);
    reduce_kernel<<<(524288 + 255) / 256, 256>>>(headout, scores, 4, 524288, 524288);

    // 11) out = headout @ Wo  (K=16384, N=5120), splitK 8 x 2048
    mma_gemm32<<<dim3(40, 8, 1), 256>>>(headout, 16384, 0, Wo, 5120, 0,
                                        part, 5120, 0, 163840, 16384, 5120, 2048);
    reduce_kernel<<<(163840 + 255) / 256, 256>>>(out, part, 8, 163840, 163840);
}

// round 16
// speedup vs baseline: 1.0337x; 1.0337x over previous
#include <cuda_runtime.h>
#include <math.h>

#define EPSF 1e-6f
#define SCALEF 0.07216878364870323f  // 1/sqrt(192)

// ---------------- device scratch ----------------
__device__ float g_qa[32 * 1536];
__device__ float g_kv[32 * 576];
__device__ float g_kvlat[32 * 512];
__device__ float g_kpe[32 * 64];
__device__ float g_q[32 * 24576];
__device__ float g_qeff[32 * 128 * 576];
__device__ float g_scores[32 * 128 * 2048];  // also reused as W_UV partial scratch
__device__ float g_headout[32 * 16384];
__device__ float g_part[8 * 1024 * 1024];
__device__ float g_rowm[4096];
__device__ float g_rowi[4096];
__device__ float g_pm[4096 * 16];
__device__ float g_ps[4096 * 16];

// ---------------- tf32 helpers ----------------
__device__ __forceinline__ unsigned f2tf(float f) {
    unsigned u;
    asm("cvt.rna.tf32.f32 %0, %1;" : "=r"(u) : "f"(f));
    return u;
}
__device__ __forceinline__ void mma_tf32(float c[4],
                                         unsigned a0, unsigned a1, unsigned a2, unsigned a3,
                                         unsigned b0, unsigned b1) {
    asm volatile("mma.sync.aligned.m16n8k8.row.col.f32.tf32.tf32.f32 "
                 "{%0,%1,%2,%3}, {%4,%5,%6,%7}, {%8,%9}, {%0,%1,%2,%3};"
                 : "+f"(c[0]), "+f"(c[1]), "+f"(c[2]), "+f"(c[3])
                 : "r"(a0), "r"(a1), "r"(a2), "r"(a3), "r"(b0), "r"(b1));
}

// =====================================================================
// tf32 MMA GEMM (double-buffered, 32x128 tile, BK=32)
// =====================================================================
__global__ __launch_bounds__(256) void mma_gemm32(
    const float* __restrict__ A, int lda, long sA,
    const float* __restrict__ B, int ldb, long sB,
    float* __restrict__ C, int ldc, long sC,
    long partStride, int K, int N, int kchunk)
{
    __shared__ unsigned As[2][32][36];
    __shared__ unsigned Bs[2][32][132];

    const int t = threadIdx.x, lane = t & 31, wid = t >> 5;
    const int warp_m = wid >> 2, warp_n = wid & 3;
    const int lq = lane >> 2, lr = lane & 3;
    const int col0 = blockIdx.x * 128;
    const int k0b = blockIdx.y * kchunk;
    const int kend = min(K, k0b + kchunk);
    const int nIter = (kend - k0b) >> 5;

    A += (long)blockIdx.z * sA;
    B += (long)blockIdx.z * sB;
    C += (long)blockIdx.z * sC + (long)blockIdx.y * partStride;

    const int am = t >> 3, akq = (t & 7) * 4;
    const int bn = (t & 31) * 4;
    const int bkb = t >> 5;
    const bool bok = (col0 + bn < N);

    float4 fa, fb[4];
    fa = *reinterpret_cast<const float4*>(&A[(long)am * lda + k0b + akq]);
#pragma unroll
    for (int i = 0; i < 4; i++) {
        int bk = bkb + i * 8;
        fb[i] = bok ? *reinterpret_cast<const float4*>(&B[(long)(k0b + bk) * ldb + col0 + bn])
                    : make_float4(0.f, 0.f, 0.f, 0.f);
    }
    *reinterpret_cast<uint4*>(&As[0][am][akq]) =
        make_uint4(f2tf(fa.x), f2tf(fa.y), f2tf(fa.z), f2tf(fa.w));
#pragma unroll
    for (int i = 0; i < 4; i++) {
        int bk = bkb + i * 8;
        *reinterpret_cast<uint4*>(&Bs[0][bk][bn]) =
            make_uint4(f2tf(fb[i].x), f2tf(fb[i].y), f2tf(fb[i].z), f2tf(fb[i].w));
    }
    __syncthreads();

    float acc[4][4];
#pragma unroll
    for (int i = 0; i < 4; i++)
#pragma unroll
        for (int j = 0; j < 4; j++) acc[i][j] = 0.f;

    for (int it = 0; it < nIter; it++) {
        const int cur = it & 1, nxt = cur ^ 1;
        const bool hasNext = (it + 1 < nIter);
        if (hasNext) {
            int kn = k0b + (it + 1) * 32;
            fa = *reinterpret_cast<const float4*>(&A[(long)am * lda + kn + akq]);
            if (bok) {
#pragma unroll
                for (int i = 0; i < 4; i++) {
                    int bk = bkb + i * 8;
                    fb[i] = *reinterpret_cast<const float4*>(&B[(long)(kn + bk) * ldb + col0 + bn]);
                }
            }
        }
#pragma unroll
        for (int kk = 0; kk < 32; kk += 8) {
            int ar = warp_m * 16 + lq;
            int ak = kk + lr;
            unsigned a0 = As[cur][ar][ak], a1 = As[cur][ar + 8][ak];
            unsigned a2 = As[cur][ar][ak + 4], a3 = As[cur][ar + 8][ak + 4];
#pragma unroll
            for (int nt8 = 0; nt8 < 4; nt8++) {
                int bnn = warp_n * 32 + nt8 * 8 + lq;
                unsigned b0 = Bs[cur][kk + lr][bnn];
                unsigned b1 = Bs[cur][kk + 4 + lr][bnn];
                mma_tf32(acc[nt8], a0, a1, a2, a3, b0, b1);
            }
        }
        if (hasNext) {
            *reinterpret_cast<uint4*>(&As[nxt][am][akq]) =
                make_uint4(f2tf(fa.x), f2tf(fa.y), f2tf(fa.z), f2tf(fa.w));
#pragma unroll
            for (int i = 0; i < 4; i++) {
                int bk = bkb + i * 8;
                *reinterpret_cast<uint4*>(&Bs[nxt][bk][bn]) =
                    make_uint4(f2tf(fb[i].x), f2tf(fb[i].y), f2tf(fb[i].z), f2tf(fb[i].w));
            }
        }
        __syncthreads();
    }
    const int row = warp_m * 16 + lq;
#pragma unroll
    for (int nt8 = 0; nt8 < 4; nt8++) {
        int col = col0 + warp_n * 32 + nt8 * 8 + 2 * lr;
        if (col < N) {
            *reinterpret_cast<float2*>(&C[(long)row * ldc + col]) =
                make_float2(acc[nt8][0], acc[nt8][1]);
            *reinterpret_cast<float2*>(&C[(long)(row + 8) * ldc + col]) =
                make_float2(acc[nt8][2], acc[nt8][3]);
        }
    }
}

// ---------------- split-K reduce ----------------
__global__ void reduce_kernel(float* __restrict__ out,
                              const float* __restrict__ part,
                              int S, long total, long stride) {
    long i = (long)blockIdx.x * 256 + threadIdx.x;
    if (i >= total) return;
    float s = 0.f;
    for (int k = 0; k < S; k++) s += part[(long)k * stride + i];
    out[i] = s;
}

// =====================================================================
// fp32 small GEMM with fused 4-way A-partial summation (W_UV)
// =====================================================================
template <int BN>
__global__ __launch_bounds__(128) void smallgemm8s(
    const float* __restrict__ A, int lda, long sA, long sumStride,
    const float* __restrict__ B, int ldb, long sB,
    float* __restrict__ C, int ldc, long sC,
    long partStride, int K, int N, int kchunk)
{
    constexpr int CN = BN / 32;
    __shared__ float As[32][36];
    __shared__ float Bs[32][BN];

    const int t = threadIdx.x;
    const int tr = t >> 5;
    const int tc = t & 31;
    const int col0 = blockIdx.x * BN;
    const int k0b = blockIdx.y * kchunk;
    const int kend = min(K, k0b + kchunk);

    A += (long)blockIdx.z * sA;
    B += (long)blockIdx.z * sB;
    C += (long)blockIdx.z * sC + (long)blockIdx.y * partStride;

    float acc[8][CN];
#pragma unroll
    for (int i = 0; i < 8; i++)
#pragma unroll
        for (int j = 0; j < CN; j++) acc[i][j] = 0.f;

    for (int k0 = k0b; k0 < kend; k0 += 32) {
#pragma unroll
        for (int i = 0; i < 2; i++) {
            int e = t + i * 128;
            int m = e >> 3, kk0 = (e & 7) * 4;
            long idx = (long)m * lda + k0 + kk0;
            float4 v = *reinterpret_cast<const float4*>(&A[idx]);
#pragma unroll
            for (int s = 1; s < 4; s++) {
                float4 w = *reinterpret_cast<const float4*>(&A[s * sumStride + idx]);
                v.x += w.x; v.y += w.y; v.z += w.z; v.w += w.w;
            }
            *reinterpret_cast<float4*>(&As[m][kk0]) = v;
        }
#pragma unroll
        for (int i = 0; i < BN / 16; i++) {
            int e = t + i * 128;
            int kk = e / (BN / 4);
            int n0 = (e % (BN / 4)) * 4;
            float4 v = make_float4(0.f, 0.f, 0.f, 0.f);
            if (col0 + n0 < N)
                v = *reinterpret_cast<const float4*>(&B[(long)(k0 + kk) * ldb + col0 + n0]);
            *reinterpret_cast<float4*>(&Bs[kk][n0]) = v;
        }
        __syncthreads();
#pragma unroll
        for (int kk = 0; kk < 32; kk++) {
            float a[8];
#pragma unroll
            for (int i = 0; i < 8; i++) a[i] = As[tr * 8 + i][kk];
            float bfr[CN];
#pragma unroll
            for (int j4 = 0; j4 < CN / 4; j4++)
                *reinterpret_cast<float4*>(&bfr[j4 * 4]) =
                    *reinterpret_cast<const float4*>(&Bs[kk][tc * CN + j4 * 4]);
#pragma unroll
            for (int i = 0; i < 8; i++)
#pragma unroll
                for (int j = 0; j < CN; j++) acc[i][j] += a[i] * bfr[j];
        }
        __syncthreads();
    }
#pragma unroll
    for (int i = 0; i < 8; i++) {
        int m = tr * 8 + i;
#pragma unroll
        for (int j4 = 0; j4 < CN / 4; j4++) {
            int col = col0 + tc * CN + j4 * 4;
            if (col < N) {
                float4 v = make_float4(acc[i][j4 * 4], acc[i][j4 * 4 + 1],
                                       acc[i][j4 * 4 + 2], acc[i][j4 * 4 + 3]);
                *reinterpret_cast<float4*>(&C[(long)m * ldc + col]) = v;
            }
        }
    }
}

// ---------------- norms + k_pe rope ----------------
__global__ void norm_rope_kernel(float* __restrict__ qa_io,
                                 const float* __restrict__ kv_in,
                                 float* __restrict__ kvlat,
                                 float* __restrict__ kpe,
                                 const float* __restrict__ q_ln_w,
                                 const float* __restrict__ kv_ln_w,
                                 const float* __restrict__ cosd,
                                 const float* __restrict__ sind) {
    const int b = blockIdx.x;
    const int t = threadIdx.x;
    __shared__ float sd[256];

    float* qa = qa_io + b * 1536;
    float ss = 0.f;
    for (int i = t; i < 1536; i += 256) { float v = qa[i]; ss += v * v; }
    sd[t] = ss; __syncthreads();
    for (int o = 128; o > 0; o >>= 1) { if (t < o) sd[t] += sd[t + o]; __syncthreads(); }
    float r = rsqrtf(sd[0] / 1536.f + EPSF);
    __syncthreads();
    for (int i = t; i < 1536; i += 256) qa[i] = qa[i] * r * q_ln_w[i];

    const float* kv = kv_in + b * 576;
    ss = 0.f;
    for (int i = t; i < 512; i += 256) { float v = kv[i]; ss += v * v; }
    sd[t] = ss; __syncthreads();
    for (int o = 128; o > 0; o >>= 1) { if (t < o) sd[t] += sd[t + o]; __syncthreads(); }
    float r2 = rsqrtf(sd[0] / 512.f + EPSF);
    __syncthreads();
    for (int i = t; i < 512; i += 256) kvlat[b * 512 + i] = kv[i] * r2 * kv_ln_w[i];

    if (t < 32) {
        float x1 = kv[512 + 2 * t], x2 = kv[512 + 2 * t + 1];
        float c = cosd[b * 32 + t], s = sind[b * 32 + t];
        kpe[b * 64 + 2 * t]     = x1 * c - x2 * s;
        kpe[b * 64 + 2 * t + 1] = x2 * c + x1 * s;
    }
}

// ---------------- rope q_pe into g_qeff[...,512:576] ----------------
__global__ void qpe_rope_kernel(const float* __restrict__ q,
                                const float* __restrict__ cosd,
                                const float* __restrict__ sind,
                                float* __restrict__ qeff) {
    int idx = blockIdx.x * 256 + threadIdx.x;
    int b = idx >> 7, h = idx & 127;
    const float* src = q + b * 24576 + h * 192 + 128;
    float* dst = qeff + (long)(b * 128 + h) * 576 + 512;
#pragma unroll
    for (int i = 0; i < 32; i++) {
        float x1 = src[2 * i], x2 = src[2 * i + 1];
        float c = cosd[b * 32 + i], s = sind[b * 32 + i];
        dst[2 * i]     = x1 * c - x2 * s;
        dst[2 * i + 1] = x2 * c + x1 * s;
    }
}

// =====================================================================
// scores (tf32 MMA, M=128, BK=16, static smem) + fused row stats.
// =====================================================================
__global__ __launch_bounds__(256) void mma_scores128(
    const float* __restrict__ qeff,
    const float* __restrict__ kvlat,
    const float* __restrict__ kpe,
    const float* __restrict__ cache_kv,
    const float* __restrict__ cache_pe,
    const int* __restrict__ block_table,
    const int* __restrict__ slot_mapping,
    const int* __restrict__ seq_lens,
    float* __restrict__ scores,
    float* __restrict__ pm,
    float* __restrict__ ps)
{
    const int nt = blockIdx.x, b = blockIdx.y;
    __shared__ unsigned As[2][128][20];    // [m][k]
    __shared__ unsigned Bs[2][16][132];    // [k][n]
    const int t = threadIdx.x, lane = t & 31, wid = t >> 5;
    const int warp_m = wid >> 1, warp_n = wid & 1;
    const int lq = lane >> 2, lr = lane & 3;

    const int blkid = block_table[b * 16 + nt];
    const int slotm = slot_mapping[b];
    const int ovr = ((slotm >> 7) == blkid) ? (slotm & 127) : -1;

    const float* Ab = qeff + (long)b * 73728;
    const float* kvb = cache_kv + (long)blkid * 65536;
    const float* peb = cache_pe + (long)blkid * 8192;

    const int am0 = t >> 2, akq = (t & 3) * 4;
    const int am1 = am0 + 64;
    const int bn0 = t >> 2, bkq = (t & 3) * 4;
    const int bn1 = bn0 + 64;

    auto fetchB = [&](int n, int kq) -> float4 {
        if (kq < 512) {
            return (n == ovr)
                ? *reinterpret_cast<const float4*>(&kvlat[b * 512 + kq])
                : *reinterpret_cast<const float4*>(&kvb[(long)n * 512 + kq]);
        } else {
            return (n == ovr)
                ? *reinterpret_cast<const float4*>(&kpe[b * 64 + (kq - 512)])
                : *reinterpret_cast<const float4*>(&peb[(long)n * 64 + (kq - 512)]);
        }
    };

    float4 fa0, fa1, fb0, fb1;
    fa0 = *reinterpret_cast<const float4*>(&Ab[(long)am0 * 576 + akq]);
    fa1 = *reinterpret_cast<const float4*>(&Ab[(long)am1 * 576 + akq]);
    fb0 = fetchB(bn0, bkq);
    fb1 = fetchB(bn1, bkq);
    *reinterpret_cast<uint4*>(&As[0][am0][akq]) =
        make_uint4(f2tf(fa0.x), f2tf(fa0.y), f2tf(fa0.z), f2tf(fa0.w));
    *reinterpret_cast<uint4*>(&As[0][am1][akq]) =
        make_uint4(f2tf(fa1.x), f2tf(fa1.y), f2tf(fa1.z), f2tf(fa1.w));
    Bs[0][bkq + 0][bn0] = f2tf(fb0.x); Bs[0][bkq + 1][bn0] = f2tf(fb0.y);
    Bs[0][bkq + 2][bn0] = f2tf(fb0.z); Bs[0][bkq + 3][bn0] = f2tf(fb0.w);
    Bs[0][bkq + 0][bn1] = f2tf(fb1.x); Bs[0][bkq + 1][bn1] = f2tf(fb1.y);
    Bs[0][bkq + 2][bn1] = f2tf(fb1.z); Bs[0][bkq + 3][bn1] = f2tf(fb1.w);
    __syncthreads();

    float acc[2][8][4];
#pragma unroll
    for (int m = 0; m < 2; m++)
#pragma unroll
        for (int i = 0; i < 8; i++)
#pragma unroll
            for (int j = 0; j < 4; j++) acc[m][i][j] = 0.f;

    const int nIter = 36;
    for (int it = 0; it < nIter; it++) {
        const int cur = it & 1, nxt = cur ^ 1;
        const bool hn = (it + 1 < nIter);
        if (hn) {
            int kn = (it + 1) * 16;
            fa0 = *reinterpret_cast<const float4*>(&Ab[(long)am0 * 576 + kn + akq]);
            fa1 = *reinterpret_cast<const float4*>(&Ab[(long)am1 * 576 + kn + akq]);
            fb0 = fetchB(bn0, kn + bkq);
            fb1 = fetchB(bn1, kn + bkq);
        }
#pragma unroll
        for (int kk = 0; kk < 16; kk += 8) {
            int ak = kk + lr;
            unsigned a[2][4];
#pragma unroll
            for (int m = 0; m < 2; m++) {
                int ar = warp_m * 32 + m * 16 + lq;
                a[m][0] = As[cur][ar][ak];      a[m][1] = As[cur][ar + 8][ak];
                a[m][2] = As[cur][ar][ak + 4];  a[m][3] = As[cur][ar + 8][ak + 4];
            }
#pragma unroll
            for (int nf = 0; nf < 8; nf++) {
                int bn = warp_n * 64 + nf * 8 + lq;
                unsigned b0 = Bs[cur][kk + lr][bn];
                unsigned b1 = Bs[cur][kk + 4 + lr][bn];
                mma_tf32(acc[0][nf], a[0][0], a[0][1], a[0][2], a[0][3], b0, b1);
                mma_tf32(acc[1][nf], a[1][0], a[1][1], a[1][2], a[1][3], b0, b1);
            }
        }
        if (hn) {
            *reinterpret_cast<uint4*>(&As[nxt][am0][akq]) =
                make_uint4(f2tf(fa0.x), f2tf(fa0.y), f2tf(fa0.z), f2tf(fa0.w));
            *reinterpret_cast<uint4*>(&As[nxt][am1][akq]) =
                make_uint4(f2tf(fa1.x), f2tf(fa1.y), f2tf(fa1.z), f2tf(fa1.w));
            Bs[nxt][bkq + 0][bn0] = f2tf(fb0.x); Bs[nxt][bkq + 1][bn0] = f2tf(fb0.y);
            Bs[nxt][bkq + 2][bn0] = f2tf(fb0.z); Bs[nxt][bkq + 3][bn0] = f2tf(fb0.w);
            Bs[nxt][bkq + 0][bn1] = f2tf(fb1.x); Bs[nxt][bkq + 1][bn1] = f2tf(fb1.y);
            Bs[nxt][bkq + 2][bn1] = f2tf(fb1.z); Bs[nxt][bkq + 3][bn1] = f2tf(fb1.w);
        }
        __syncthreads();
    }

    // ------------- epilogue: scores write + fused per-block row stats -------
    float* smax = reinterpret_cast<float*>(As);   // [128][2]
    float* ssum = smax + 256;                     // [128][2]
    const int L = seq_lens[b];

#pragma unroll
    for (int m = 0; m < 2; m++) {
        float m0 = -1e30f, m1 = -1e30f;
#pragma unroll
        for (int nf = 0; nf < 8; nf++) {
            int col = nt * 128 + warp_n * 64 + nf * 8 + 2 * lr;
            float v00 = (col < L)     ? acc[m][nf][0] * SCALEF : -1e30f;
            float v01 = (col + 1 < L) ? acc[m][nf][1] * SCALEF : -1e30f;
            float v10 = (col < L)     ? acc[m][nf][2] * SCALEF : -1e30f;
            float v11 = (col + 1 < L) ? acc[m][nf][3] * SCALEF : -1e30f;
            m0 = fmaxf(m0, fmaxf(v00, v01));
            m1 = fmaxf(m1, fmaxf(v10, v11));
        }
        m0 = fmaxf(m0, __shfl_xor_sync(0xffffffffu, m0, 1));
        m0 = fmaxf(m0, __shfl_xor_sync(0xffffffffu, m0, 2));
        m1 = fmaxf(m1, __shfl_xor_sync(0xffffffffu, m1, 1));
        m1 = fmaxf(m1, __shfl_xor_sync(0xffffffffu, m1, 2));
        if (lr == 0) {
            int rl0 = warp_m * 32 + m * 16 + lq;
            smax[rl0 * 2 + warp_n] = m0;
            smax[(rl0 + 8) * 2 + warp_n] = m1;
        }
    }
    __syncthreads();

#pragma unroll
    for (int m = 0; m < 2; m++) {
        int rl0 = warp_m * 32 + m * 16 + lq;
        float rm0 = fmaxf(smax[rl0 * 2], smax[rl0 * 2 + 1]);
        float rm1 = fmaxf(smax[(rl0 + 8) * 2], smax[(rl0 + 8) * 2 + 1]);
        float s0 = 0.f, s1 = 0.f;
        const long row0 = (long)(b * 128 + rl0);
#pragma unroll
        for (int nf = 0; nf < 8; nf++) {
            int col = nt * 128 + warp_n * 64 + nf * 8 + 2 * lr;
            float v00 = acc[m][nf][0] * SCALEF, v01 = acc[m][nf][1] * SCALEF;
            float v10 = acc[m][nf][2] * SCALEF, v11 = acc[m][nf][3] * SCALEF;
            if (col < L)     { s0 += __expf(v00 - rm0); s1 += __expf(v10 - rm1); }
            if (col + 1 < L) { s0 += __expf(v01 - rm0); s1 += __expf(v11 - rm1); }
            *reinterpret_cast<float2*>(&scores[row0 * 2048 + col]) = make_float2(v00, v01);
            *reinterpret_cast<float2*>(&scores[(row0 + 8) * 2048 + col]) = make_float2(v10, v11);
        }
        s0 += __shfl_xor_sync(0xffffffffu, s0, 1);
        s0 += __shfl_xor_sync(0xffffffffu, s0, 2);
        s1 += __shfl_xor_sync(0xffffffffu, s1, 1);
        s1 += __shfl_xor_sync(0xffffffffu, s1, 2);
        if (lr == 0) {
            ssum[rl0 * 2 + warp_n] = s0;
            ssum[(rl0 + 8) * 2 + warp_n] = s1;
        }
    }
    __syncthreads();

    if (warp_n == 0 && lr == 0) {
#pragma unroll
        for (int m = 0; m < 2; m++) {
            int rl0 = warp_m * 32 + m * 16 + lq;
            int rl1 = rl0 + 8;
            float rm0 = fmaxf(smax[rl0 * 2], smax[rl0 * 2 + 1]);
            float rm1 = fmaxf(smax[rl1 * 2], smax[rl1 * 2 + 1]);
            pm[(long)(b * 128 + rl0) * 16 + nt] = rm0;
            pm[(long)(b * 128 + rl1) * 16 + nt] = rm1;
            ps[(long)(b * 128 + rl0) * 16 + nt] = ssum[rl0 * 2] + ssum[rl0 * 2 + 1];
            ps[(long)(b * 128 + rl1) * 16 + nt] = ssum[rl1 * 2] + ssum[rl1 * 2 + 1];
        }
    }
}

// ---------------- combine per-block partials -> rowM, rowI ----------------
__global__ void combine_rowstat(const float* __restrict__ pm,
                                const float* __restrict__ ps,
                                float* __restrict__ rowM,
                                float* __restrict__ rowI) {
    int row = blockIdx.x * 256 + threadIdx.x;
    if (row >= 4096) return;
    float M = -1e30f;
#pragma unroll
    for (int i = 0; i < 16; i++) M = fmaxf(M, pm[row * 16 + i]);
    float S = 0.f;
#pragma unroll
    for (int i = 0; i < 16; i++) S += ps[row * 16 + i] * __expf(pm[row * 16 + i] - M);
    rowM[row] = M;
    rowI[row] = 1.f / S;
}

// =====================================================================
// ctx (tf32 MMA, M=128 head tile + token split-K, fused softmax staging)
// =====================================================================
__global__ __launch_bounds__(256) void mma_ctx128(
    const float* __restrict__ scores,
    const float* __restrict__ kvlat,
    const float* __restrict__ cache_kv,
    const int* __restrict__ block_table,
    const int* __restrict__ slot_mapping,
    const int* __restrict__ seq_lens,
    const float* __restrict__ rowM,
    const float* __restrict__ rowI,
    float* __restrict__ part)
{
    const int nt = blockIdx.x, sk = blockIdx.y, b = blockIdx.z;
    __shared__ unsigned As[2][128][20];
    __shared__ unsigned Bs[2][16][132];
    const int t = threadIdx.x, lane = t & 31, wid = t >> 5;
    const int warp_m = wid >> 1, warp_n = wid & 1;
    const int lq = lane >> 2, lr = lane & 3;
    const int slotm = slot_mapping[b];
    const int ovrBlk = slotm >> 7, ovrOff = slotm & 127;
    const int L = seq_lens[b];
    const int tk0 = sk * 512;

    const int am0 = t >> 2, akq = (t & 3) * 4;
    const int am1 = am0 + 64;
    const long arow0 = (long)(b * 128 + am0);
    const long arow1 = (long)(b * 128 + am1);
    const float rm0 = rowM[arow0], ri0 = rowI[arow0];
    const float rm1 = rowM[arow1], ri1 = rowI[arow1];

    const int bkk0 = t >> 5, bn0 = (t & 31) * 4;
    const int bkk1 = (t + 256) >> 5, bn1 = bn0;

    auto xformA = [&](float4 v, float rm, float ri, int kbase) -> uint4 {
        float e0 = (kbase + 0 < L) ? __expf(v.x - rm) * ri : 0.f;
        float e1 = (kbase + 1 < L) ? __expf(v.y - rm) * ri : 0.f;
        float e2 = (kbase + 2 < L) ? __expf(v.z - rm) * ri : 0.f;
        float e3 = (kbase + 3 < L) ? __expf(v.w - rm) * ri : 0.f;
        return make_uint4(f2tf(e0), f2tf(e1), f2tf(e2), f2tf(e3));
    };

    auto fetchB = [&](int k0, int kk, int n0) -> float4 {
        int tok = tk0 + k0 + kk;
        int blkid = block_table[b * 16 + (tok >> 7)];
        int soff = tok & 127;
        if (blkid == ovrBlk && soff == ovrOff)
            return *reinterpret_cast<const float4*>(&kvlat[b * 512 + nt * 128 + n0]);
        return *reinterpret_cast<const float4*>(
            &cache_kv[(long)(blkid * 128 + soff) * 512 + nt * 128 + n0]);
    };

    float4 fa0, fa1, fb0, fb1;
    fa0 = *reinterpret_cast<const float4*>(&scores[arow0 * 2048 + tk0 + akq]);
    fa1 = *reinterpret_cast<const float4*>(&scores[arow1 * 2048 + tk0 + akq]);
    fb0 = fetchB(0, bkk0, bn0);
    fb1 = fetchB(0, bkk1, bn1);
    *reinterpret_cast<uint4*>(&As[0][am0][akq]) = xformA(fa0, rm0, ri0, tk0 + akq);
    *reinterpret_cast<uint4*>(&As[0][am1][akq]) = xformA(fa1, rm1, ri1, tk0 + akq);
    *reinterpret_cast<uint4*>(&Bs[0][bkk0][bn0]) =
        make_uint4(f2tf(fb0.x), f2tf(fb0.y), f2tf(fb0.z), f2tf(fb0.w));
    *reinterpret_cast<uint4*>(&Bs[0][bkk1][bn1]) =
        make_uint4(f2tf(fb1.x), f2tf(fb1.y), f2tf(fb1.z), f2tf(fb1.w));
    __syncthreads();

    float acc[2][8][4];
#pragma unroll
    for (int m = 0; m < 2; m++)
#pragma unroll
        for (int i = 0; i < 8; i++)
#pragma unroll
            for (int j = 0; j < 4; j++) acc[m][i][j] = 0.f;

    const int nIter = 32;
    for (int it = 0; it < nIter; it++) {
        const int cur = it & 1, nxt = cur ^ 1;
        const bool hn = (it + 1 < nIter);
        int kn = (it + 1) * 16;
        if (hn) {
            fa0 = *reinterpret_cast<const float4*>(&scores[arow0 * 2048 + tk0 + kn + akq]);
            fa1 = *reinterpret_cast<const float4*>(&scores[arow1 * 2048 + tk0 + kn + akq]);
            fb0 = fetchB(kn, bkk0, bn0);
            fb1 = fetchB(kn, bkk1, bn1);
        }
#pragma unroll
        for (int kk = 0; kk < 16; kk += 8) {
            int ak = kk + lr;
            unsigned a[2][4];
#pragma unroll
            for (int m = 0; m < 2; m++) {
                int ar = warp_m * 32 + m * 16 + lq;
                a[m][0] = As[cur][ar][ak];      a[m][1] = As[cur][ar + 8][ak];
                a[m][2] = As[cur][ar][ak + 4];  a[m][3] = As[cur][ar + 8][ak + 4];
            }
#pragma unroll
            for (int nf = 0; nf < 8; nf++) {
                int bn = warp_n * 64 + nf * 8 + lq;
                unsigned b0 = Bs[cur][kk + lr][bn];
                unsigned b1 = Bs[cur][kk + 4 + lr][bn];
                mma_tf32(acc[0][nf], a[0][0], a[0][1], a[0][2], a[0][3], b0, b1);
                mma_tf32(acc[1][nf], a[1][0], a[1][1], a[1][2], a[1][3], b0, b1);
            }
        }
        if (hn) {
            *reinterpret_cast<uint4*>(&As[nxt][am0][akq]) = xformA(fa0, rm0, ri0, tk0 + kn + akq);
            *reinterpret_cast<uint4*>(&As[nxt][am1][akq]) = xformA(fa1, rm1, ri1, tk0 + kn + akq);
            *reinterpret_cast<uint4*>(&Bs[nxt][bkk0][bn0]) =
                make_uint4(f2tf(fb0.x), f2tf(fb0.y), f2tf(fb0.z), f2tf(fb0.w));
            *reinterpret_cast<uint4*>(&Bs[nxt][bkk1][bn1]) =
                make_uint4(f2tf(fb1.x), f2tf(fb1.y), f2tf(fb1.z), f2tf(fb1.w));
        }
        __syncthreads();
    }
    float* outp = part + (long)sk * 2097152;
#pragma unroll
    for (int m = 0; m < 2; m++) {
        const long row0 = (long)(b * 128 + warp_m * 32 + m * 16 + lq);
#pragma unroll
        for (int nf = 0; nf < 8; nf++) {
            int col = nt * 128 + warp_n * 64 + nf * 8 + 2 * lr;
            *reinterpret_cast<float2*>(&outp[row0 * 512 + col]) =
                make_float2(acc[m][nf][0], acc[m][nf][1]);
            *reinterpret_cast<float2*>(&outp[(row0 + 8) * 512 + col]) =
                make_float2(acc[m][nf][2], acc[m][nf][3]);
        }
    }
}

// ------------------------------ host driver ------------------------------
extern "C" void kernel_launch(void* const* d_in, const int* in_sizes, int n_in,
                              void* d_out, int out_size) {
    const float* hidden    = (const float*)d_in[0];
    const float* cosd      = (const float*)d_in[1];
    const float* sind      = (const float*)d_in[2];
    const float* Wq_a      = (const float*)d_in[3];
    const float* q_ln_w    = (const float*)d_in[4];
    const float* Wq_b      = (const float*)d_in[5];
    const float* Wkv_a     = (const float*)d_in[6];
    const float* kv_ln_w   = (const float*)d_in[7];
    const float* Wukt      = (const float*)d_in[8];
    const float* Wuv       = (const float*)d_in[9];
    const float* Wo        = (const float*)d_in[10];
    const float* cache_kv  = (const float*)d_in[11];
    const float* cache_pe  = (const float*)d_in[12];
    const int*   block_tab = (const int*)d_in[13];
    const int*   slot_map  = (const int*)d_in[14];
    const int*   seq_lens  = (const int*)d_in[15];
    float* out = (float*)d_out;

    float *qa, *kvb, *kvlat, *kpe, *q, *qeff, *scores, *headout, *part;
    float *rowm, *rowi, *pm, *ps;
    cudaGetSymbolAddress((void**)&qa,      g_qa);
    cudaGetSymbolAddress((void**)&kvb,     g_kv);
    cudaGetSymbolAddress((void**)&kvlat,   g_kvlat);
    cudaGetSymbolAddress((void**)&kpe,     g_kpe);
    cudaGetSymbolAddress((void**)&q,       g_q);
    cudaGetSymbolAddress((void**)&qeff,    g_qeff);
    cudaGetSymbolAddress((void**)&scores,  g_scores);
    cudaGetSymbolAddress((void**)&headout, g_headout);
    cudaGetSymbolAddress((void**)&part,    g_part);
    cudaGetSymbolAddress((void**)&rowm,    g_rowm);
    cudaGetSymbolAddress((void**)&rowi,    g_rowi);
    cudaGetSymbolAddress((void**)&pm,      g_pm);
    cudaGetSymbolAddress((void**)&ps,      g_ps);

    // 1) q_a = hidden @ Wq_a  (K=5120, N=1536), splitK 16 x 320
    mma_gemm32<<<dim3(12, 16, 1), 256>>>(hidden, 5120, 0, Wq_a, 1536, 0,
                                         part, 1536, 0, 49152, 5120, 1536, 320);
    reduce_kernel<<<(49152 + 255) / 256, 256>>>(qa, part, 16, 49152, 49152);

    // 2) kv = hidden @ Wkv_a  (K=5120, N=576), splitK 16 x 320
    mma_gemm32<<<dim3(5, 16, 1), 256>>>(hidden, 5120, 0, Wkv_a, 576, 0,
                                        part, 576, 0, 18432, 5120, 576, 320);
    reduce_kernel<<<(18432 + 255) / 256, 256>>>(kvb, part, 16, 18432, 18432);

    // 3) norms + k_pe rope
    norm_rope_kernel<<<32, 256>>>(qa, kvb, kvlat, kpe, q_ln_w, kv_ln_w, cosd, sind);

    // 4) q = q_a_norm @ Wq_b  (K=1536, N=24576), splitK 4 x 384 (768 CTAs)
    mma_gemm32<<<dim3(192, 4, 1), 256>>>(qa, 1536, 0, Wq_b, 24576, 0,
                                         part, 24576, 0, 786432, 1536, 24576, 384);
    reduce_kernel<<<(786432 + 255) / 256, 256>>>(q, part, 4, 786432, 786432);

    // 5) rope q_pe -> qeff[..., 512:576]
    qpe_rope_kernel<<<16, 256>>>(q, cosd, sind, qeff);

    // 6) q_lat[b,h,:512] = q_nope[b,h] @ W_UK_T[h]  (per-head, tf32 MMA)
    mma_gemm32<<<dim3(4, 1, 128), 256>>>(q, 24576, 192, Wukt, 512, 65536,
                                         qeff, 73728, 576, 0, 128, 512, 128);

    // 7) attention scores + fused per-block row stats (512 CTAs)
    mma_scores128<<<dim3(16, 32), 256>>>(qeff, kvlat, kpe, cache_kv, cache_pe,
                                         block_tab, slot_map, seq_lens,
                                         scores, pm, ps);

    // 8) combine partials -> rowM, rowI
    combine_rowstat<<<16, 256>>>(pm, ps, rowm, rowi);

    // 9) ctx partials = softmax(scores) @ keys_kv (M=128, token splitK 4)
    mma_ctx128<<<dim3(4, 4, 32), 256>>>(scores, kvlat, cache_kv, block_tab,
                                        slot_map, seq_lens, rowm, rowi, part);

    // 10) headout = (sum of ctx partials) @ W_UV, fused A-sum
    smallgemm8s<128><<<dim3(1, 4, 128), 128>>>(part, 65536, 512, 2097152,
                                               Wuv, 128, 65536,
                                               scores, 16384, 128, 524288,
                                               512, 128, 128);
    reduce_kernel<<<(524288 + 255) / 256, 256>>>(headout, scores, 4, 524288, 524288);

    // 11) out = headout @ Wo  (K=16384, N=5120), splitK 16 x 1024 (640 CTAs)
    mma_gemm32<<<dim3(40, 16, 1), 256>>>(headout, 16384, 0, Wo, 5120, 0,
                                         part, 5120, 0, 163840, 16384, 5120, 1024);
    reduce_kernel<<<(163840 + 255) / 256, 256>>>(out, part, 16, 163840, 163840);
}